// round 14
// baseline (speedup 1.0000x reference)
#include <cuda_runtime.h>
#include <math.h>

#define NTOK 4096
#define DDIM 1024
#define NE 8
#define HDIM 1024
#define SLOTCAP 9216
#define CHUNK 512
#define NCHUNK (SLOTCAP / CHUNK)   // 18
#define NBLK 148

// ---------------- scratch (device globals, ~2.2 MB total) ----------------
// NOTE: no __device__ symbol is ever referenced from host code.
__device__ int   g_cnt[NE];
__device__ int   g_cnt2[NE];
__device__ int   g_offr[NE];               // 64-aligned slot offsets
__device__ float g_gates_sum[NE];
__device__ float g_probs_sum[NE];
__device__ float g_zsum;
__device__ int   g_top_i[NTOK * 2];
__device__ float g_top_g[NTOK * 2];
__device__ int   g_tok[SLOTCAP];
__device__ float g_gate[SLOTCAP];
__device__ float g_hc[CHUNK * HDIM];       // 2 MB chunk buffer

// ---------------- zero counters ----------------
__global__ void zero_kernel() {
    int t = threadIdx.x;
    if (t < NE) { g_cnt[t] = 0; g_cnt2[t] = 0; g_gates_sum[t] = 0.f; g_probs_sum[t] = 0.f; }
    if (t == NE) g_zsum = 0.f;
}

// ---------------- persistent zero of out's y region ----------------
__global__ void __launch_bounds__(256) zero_out_kernel(float* __restrict__ out) {
    float4* o4 = (float4*)out;
    const int total = NTOK * DDIM / 4;
    for (int i = blockIdx.x * 256 + threadIdx.x; i < total; i += NBLK * 256)
        o4[i] = make_float4(0.f, 0.f, 0.f, 0.f);
}

// ---------------- gating: logits GEMV + noisy softmax + top2 + loss sums ----------------
__global__ void __launch_bounds__(128) gating_kernel(
        const float* __restrict__ x, const float* __restrict__ wg,
        const float* __restrict__ eps) {
    __shared__ float xs[32][68];
    __shared__ float wgs[16][64];
    __shared__ float sh_logits[32][17];
    __shared__ float sh_probs[NE], sh_gates[NE], sh_z;
    __shared__ int   sh_cnt[NE];

    int tid = threadIdx.x;
    int tq = tid & 31, og = tid >> 5;
    if (tid < NE) { sh_probs[tid] = 0.f; sh_gates[tid] = 0.f; sh_cnt[tid] = 0; }
    if (tid == NE) sh_z = 0.f;

    int tokbase = blockIdx.x * 32;
    float acc0 = 0.f, acc1 = 0.f, acc2 = 0.f, acc3 = 0.f;

    for (int k0 = 0; k0 < DDIM; k0 += 64) {
        __syncthreads();
        #pragma unroll
        for (int idx = tid; idx < 32 * 64; idx += 128) {
            int tk = idx >> 6, kk = idx & 63;
            xs[tk][kk] = x[(size_t)(tokbase + tk) * DDIM + k0 + kk];
        }
        #pragma unroll
        for (int idx = tid; idx < 16 * 64; idx += 128) {
            int o = idx >> 6, kk = idx & 63;
            wgs[o][kk] = wg[(size_t)o * DDIM + k0 + kk];
        }
        __syncthreads();
        #pragma unroll
        for (int kk = 0; kk < 64; kk += 4) {
            float4 xv = *(const float4*)&xs[tq][kk];
            float4 w0 = *(const float4*)&wgs[og * 4 + 0][kk];
            float4 w1v = *(const float4*)&wgs[og * 4 + 1][kk];
            float4 w2v = *(const float4*)&wgs[og * 4 + 2][kk];
            float4 w3 = *(const float4*)&wgs[og * 4 + 3][kk];
            acc0 += xv.x * w0.x + xv.y * w0.y + xv.z * w0.z + xv.w * w0.w;
            acc1 += xv.x * w1v.x + xv.y * w1v.y + xv.z * w1v.z + xv.w * w1v.w;
            acc2 += xv.x * w2v.x + xv.y * w2v.y + xv.z * w2v.z + xv.w * w2v.w;
            acc3 += xv.x * w3.x + xv.y * w3.y + xv.z * w3.z + xv.w * w3.w;
        }
    }
    __syncthreads();
    sh_logits[tq][og * 4 + 0] = acc0;
    sh_logits[tq][og * 4 + 1] = acc1;
    sh_logits[tq][og * 4 + 2] = acc2;
    sh_logits[tq][og * 4 + 3] = acc3;
    __syncthreads();

    if (tid < 32) {
        int n = tokbase + tid;
        auto mk = [&](int e) -> float {
            float clean = sh_logits[tid][e];
            float raw   = sh_logits[tid][e + NE];
            float sp = (raw > 20.f) ? raw : __logf(1.f + __expf(raw));
            return clean + eps[(size_t)n * NE + e] * (sp + 0.01f);
        };
        float l0 = mk(0), l1 = mk(1), l2 = mk(2), l3 = mk(3);
        float l4 = mk(4), l5 = mk(5), l6 = mk(6), l7 = mk(7);

        float mx = fmaxf(fmaxf(fmaxf(l0, l1), fmaxf(l2, l3)),
                         fmaxf(fmaxf(l4, l5), fmaxf(l6, l7)));
        float p0 = __expf(l0 - mx), p1 = __expf(l1 - mx);
        float p2 = __expf(l2 - mx), p3 = __expf(l3 - mx);
        float p4 = __expf(l4 - mx), p5 = __expf(l5 - mx);
        float p6 = __expf(l6 - mx), p7 = __expf(l7 - mx);
        float s = p0 + p1 + p2 + p3 + p4 + p5 + p6 + p7;
        float inv = __fdividef(1.f, s);
        float lse = mx + __logf(s);

        float v0 = -1e30f, v1 = -1e30f;
        int i0 = 0, i1 = 0;
        auto upd = [&](float l, int e) {
            bool gt0 = l > v0;
            bool gt1 = l > v1;
            v1 = gt0 ? v0 : (gt1 ? l : v1);
            i1 = gt0 ? i0 : (gt1 ? e : i1);
            v0 = gt0 ? l : v0;
            i0 = gt0 ? e : i0;
        };
        upd(l0, 0); upd(l1, 1); upd(l2, 2); upd(l3, 3);
        upd(l4, 4); upd(l5, 5); upd(l6, 6); upd(l7, 7);

        float gv0 = __expf(v0 - mx) * inv;
        float gv1 = __expf(v1 - mx) * inv;

        atomicAdd(&sh_probs[0], p0 * inv); atomicAdd(&sh_probs[1], p1 * inv);
        atomicAdd(&sh_probs[2], p2 * inv); atomicAdd(&sh_probs[3], p3 * inv);
        atomicAdd(&sh_probs[4], p4 * inv); atomicAdd(&sh_probs[5], p5 * inv);
        atomicAdd(&sh_probs[6], p6 * inv); atomicAdd(&sh_probs[7], p7 * inv);
        atomicAdd(&sh_z, lse * lse);
        atomicAdd(&sh_gates[i0], gv0);
        atomicAdd(&sh_gates[i1], gv1);
        atomicAdd(&sh_cnt[i0], 1);
        atomicAdd(&sh_cnt[i1], 1);
        g_top_i[2 * n]     = i0;  g_top_g[2 * n]     = gv0;
        g_top_i[2 * n + 1] = i1;  g_top_g[2 * n + 1] = gv1;
    }
    __syncthreads();
    if (tid < NE) {
        atomicAdd(&g_cnt[tid], sh_cnt[tid]);
        atomicAdd(&g_probs_sum[tid], sh_probs[tid]);
        atomicAdd(&g_gates_sum[tid], sh_gates[tid]);
    }
    if (tid == NE) atomicAdd(&g_zsum, sh_z);
}

// ---------------- offsets: 64-aligned prefix sum ----------------
__global__ void offsets_kernel() {
    int off = 0;
    #pragma unroll
    for (int e = 0; e < NE; e++) {
        g_offr[e] = off;
        off += ((g_cnt[e] + 63) >> 6) << 6;
    }
}

// ---------------- scatter ----------------
__global__ void __launch_bounds__(256) scatter_kernel() {
    int n = blockIdx.x * 256 + threadIdx.x;
    if (n >= NTOK) return;
    #pragma unroll
    for (int k = 0; k < 2; k++) {
        int e = g_top_i[2 * n + k];
        int pos = atomicAdd(&g_cnt2[e], 1);
        int s = g_offr[e] + pos;
        g_tok[s]  = n;
        g_gate[s] = g_top_g[2 * n + k];
    }
}

// Decode expert for a 64-aligned slot-row tile start. Returns -1 if beyond total.
__device__ __forceinline__ int find_expert(int srow) {
    int e = 0;
    #pragma unroll
    for (int q = 1; q < NE; q++) if (srow >= g_offr[q]) e = q;
    int rsz = ((g_cnt[e] + 63) >> 6) << 6;
    return (srow < g_offr[e] + rsz) ? e : -1;
}

// ---------------- GEMM1 chunk: g_hc[local] = gate * relu( X[tok] @ w1[e] ) ----------------
// grid (16, 8) x 256 threads; 64x64x8 tile, 16 named scalar accumulators.
__global__ void __launch_bounds__(256, 1) gemm1_chunk(
        const float* __restrict__ x, const float* __restrict__ w1, int chunk) {
    const int srow = chunk * CHUNK + blockIdx.y * 64;
    const int e = find_expert(srow);
    if (e < 0) return;
    const int M = g_cnt[e];
    const int base_e = srow - g_offr[e];
    if (base_e >= M) return;                    // pure padding tile
    const int nbase = blockIdx.x * 64;

    __shared__ __align__(16) float As[8][64];
    __shared__ __align__(16) float Bs[8][64];

    int tid = threadIdx.x;
    int a_row = tid >> 2, a_k = (tid & 3) << 1;
    int b_k = tid >> 5, b_n = (tid & 31) << 1;
    int tx = tid & 15, ty = tid >> 4;

    int r_e = min(base_e + a_row, M - 1);
    int tok = g_tok[g_offr[e] + r_e];
    const float* Arow = x + (size_t)tok * DDIM + a_k;
    const float* Bptr = w1 + (size_t)e * DDIM * HDIM + (size_t)b_k * HDIM + nbase + b_n;

    float c00 = 0.f, c01 = 0.f, c02 = 0.f, c03 = 0.f;
    float c10 = 0.f, c11 = 0.f, c12 = 0.f, c13 = 0.f;
    float c20 = 0.f, c21 = 0.f, c22 = 0.f, c23 = 0.f;
    float c30 = 0.f, c31 = 0.f, c32 = 0.f, c33 = 0.f;

    for (int k0 = 0; k0 < DDIM; k0 += 8) {
        float2 av = *(const float2*)(Arow + k0);
        float2 bv = *(const float2*)(Bptr + (size_t)k0 * HDIM);
        __syncthreads();
        As[a_k + 0][a_row] = av.x;
        As[a_k + 1][a_row] = av.y;
        Bs[b_k][b_n + 0] = bv.x;
        Bs[b_k][b_n + 1] = bv.y;
        __syncthreads();
        #pragma unroll
        for (int k = 0; k < 8; k++) {
            float4 a = *(const float4*)&As[k][ty * 4];
            float4 b = *(const float4*)&Bs[k][tx * 4];
            c00 += a.x * b.x; c01 += a.x * b.y; c02 += a.x * b.z; c03 += a.x * b.w;
            c10 += a.y * b.x; c11 += a.y * b.y; c12 += a.y * b.z; c13 += a.y * b.w;
            c20 += a.z * b.x; c21 += a.z * b.y; c22 += a.z * b.z; c23 += a.z * b.w;
            c30 += a.w * b.x; c31 += a.w * b.y; c32 += a.w * b.z; c33 += a.w * b.w;
        }
    }

    int lrow0 = blockIdx.y * 64 + ty * 4;       // row within chunk buffer
    int gm0 = base_e + ty * 4;                  // row within expert
    float* C0 = g_hc + (size_t)lrow0 * HDIM + nbase + tx * 4;
    if (gm0 < M) {
        float g = g_gate[g_offr[e] + gm0];
        *(float4*)C0 = make_float4(fmaxf(c00,0.f)*g, fmaxf(c01,0.f)*g, fmaxf(c02,0.f)*g, fmaxf(c03,0.f)*g);
    }
    if (gm0 + 1 < M) {
        float g = g_gate[g_offr[e] + gm0 + 1];
        *(float4*)(C0 + HDIM) = make_float4(fmaxf(c10,0.f)*g, fmaxf(c11,0.f)*g, fmaxf(c12,0.f)*g, fmaxf(c13,0.f)*g);
    }
    if (gm0 + 2 < M) {
        float g = g_gate[g_offr[e] + gm0 + 2];
        *(float4*)(C0 + 2 * HDIM) = make_float4(fmaxf(c20,0.f)*g, fmaxf(c21,0.f)*g, fmaxf(c22,0.f)*g, fmaxf(c23,0.f)*g);
    }
    if (gm0 + 3 < M) {
        float g = g_gate[g_offr[e] + gm0 + 3];
        *(float4*)(C0 + 3 * HDIM) = make_float4(fmaxf(c30,0.f)*g, fmaxf(c31,0.f)*g, fmaxf(c32,0.f)*g, fmaxf(c33,0.f)*g);
    }
}

// ---------------- GEMM2 chunk: atomicAdd( out[tok], g_hc[local] @ w2[e] ) ----------------
__global__ void __launch_bounds__(256, 1) gemm2_chunk(
        const float* __restrict__ w2, float* __restrict__ out, int chunk) {
    const int srow = chunk * CHUNK + blockIdx.y * 64;
    const int e = find_expert(srow);
    if (e < 0) return;
    const int M = g_cnt[e];
    const int base_e = srow - g_offr[e];
    if (base_e >= M) return;
    const int nbase = blockIdx.x * 64;

    __shared__ __align__(16) float As[8][64];
    __shared__ __align__(16) float Bs[8][64];

    int tid = threadIdx.x;
    int a_row = tid >> 2, a_k = (tid & 3) << 1;
    int b_k = tid >> 5, b_n = (tid & 31) << 1;
    int tx = tid & 15, ty = tid >> 4;

    int r_e = min(base_e + a_row, M - 1);
    int lidx = g_offr[e] + r_e - chunk * CHUNK;      // row within chunk buffer
    lidx = min(max(lidx, 0), CHUNK - 1);             // safety clamp (padding rows)
    const float* Arow = g_hc + (size_t)lidx * HDIM + a_k;
    const float* Bptr = w2 + (size_t)e * HDIM * DDIM + (size_t)b_k * DDIM + nbase + b_n;

    float c00 = 0.f, c01 = 0.f, c02 = 0.f, c03 = 0.f;
    float c10 = 0.f, c11 = 0.f, c12 = 0.f, c13 = 0.f;
    float c20 = 0.f, c21 = 0.f, c22 = 0.f, c23 = 0.f;
    float c30 = 0.f, c31 = 0.f, c32 = 0.f, c33 = 0.f;

    for (int k0 = 0; k0 < HDIM; k0 += 8) {
        float2 av = *(const float2*)(Arow + k0);
        float2 bv = *(const float2*)(Bptr + (size_t)k0 * DDIM);
        __syncthreads();
        As[a_k + 0][a_row] = av.x;
        As[a_k + 1][a_row] = av.y;
        Bs[b_k][b_n + 0] = bv.x;
        Bs[b_k][b_n + 1] = bv.y;
        __syncthreads();
        #pragma unroll
        for (int k = 0; k < 8; k++) {
            float4 a = *(const float4*)&As[k][ty * 4];
            float4 b = *(const float4*)&Bs[k][tx * 4];
            c00 += a.x * b.x; c01 += a.x * b.y; c02 += a.x * b.z; c03 += a.x * b.w;
            c10 += a.y * b.x; c11 += a.y * b.y; c12 += a.y * b.z; c13 += a.y * b.w;
            c20 += a.z * b.x; c21 += a.z * b.y; c22 += a.z * b.z; c23 += a.z * b.w;
            c30 += a.w * b.x; c31 += a.w * b.y; c32 += a.w * b.z; c33 += a.w * b.w;
        }
    }

    int gm0 = base_e + ty * 4;
    int col = nbase + tx * 4;
    if (gm0 < M) {
        float* d = out + (size_t)g_tok[g_offr[e] + gm0] * DDIM + col;
        atomicAdd(d + 0, c00); atomicAdd(d + 1, c01); atomicAdd(d + 2, c02); atomicAdd(d + 3, c03);
    }
    if (gm0 + 1 < M) {
        float* d = out + (size_t)g_tok[g_offr[e] + gm0 + 1] * DDIM + col;
        atomicAdd(d + 0, c10); atomicAdd(d + 1, c11); atomicAdd(d + 2, c12); atomicAdd(d + 3, c13);
    }
    if (gm0 + 2 < M) {
        float* d = out + (size_t)g_tok[g_offr[e] + gm0 + 2] * DDIM + col;
        atomicAdd(d + 0, c20); atomicAdd(d + 1, c21); atomicAdd(d + 2, c22); atomicAdd(d + 3, c23);
    }
    if (gm0 + 3 < M) {
        float* d = out + (size_t)g_tok[g_offr[e] + gm0 + 3] * DDIM + col;
        atomicAdd(d + 0, c30); atomicAdd(d + 1, c31); atomicAdd(d + 2, c32); atomicAdd(d + 3, c33);
    }
}

// ---------------- loss finalize ----------------
__global__ void loss_kernel(float* __restrict__ out, int out_size) {
    if (out_size <= NTOK * DDIM) return;
    float T = 0.f, P = 0.f, C = 0.f;
    #pragma unroll
    for (int e = 0; e < NE; e++) {
        T += fabsf(g_gates_sum[e]);
        P += fabsf(g_probs_sum[e]);
        C += fabsf((float)g_cnt[e]);
    }
    T = fmaxf(T, 1e-12f); P = fmaxf(P, 1e-12f); C = fmaxf(C, 1e-12f);
    float rT = __fdividef(1.f, T);
    float rP = __fdividef(1.f, P);
    float rC = __fdividef(1.f, C);
    float mean = 0.f;
    #pragma unroll
    for (int e = 0; e < NE; e++) mean += g_gates_sum[e] * rT;
    mean *= 0.125f;
    float var = 0.f;
    #pragma unroll
    for (int e = 0; e < NE; e++) {
        float d = g_gates_sum[e] * rT - mean;
        var += d * d;
    }
    var *= (1.f / (float)(NE - 1));
    float cv = __fdividef(var, mean * mean + 1e-10f);
    float sw = 0.f;
    #pragma unroll
    for (int e = 0; e < NE; e++)
        sw += (g_probs_sum[e] * rP) * ((float)g_cnt[e] * rC);
    sw = (1.f - sw) * (float)NE;
    float z = g_zsum * (1.f / (float)NTOK);
    out[NTOK * DDIM] = 0.01f * cv + 0.1f * sw + 0.0001f * z;
}

// ---------------- launch ----------------
extern "C" void kernel_launch(void* const* d_in, const int* in_sizes, int n_in,
                              void* d_out, int out_size) {
    const float* x   = (const float*)d_in[0];
    const float* wg  = (const float*)d_in[1];
    const float* w1  = (const float*)d_in[2];
    const float* w2  = (const float*)d_in[3];
    const float* eps = (const float*)d_in[4];
    float* out = (float*)d_out;

    zero_kernel<<<1, 32>>>();
    zero_out_kernel<<<NBLK, 256>>>(out);
    gating_kernel<<<128, 128>>>(x, wg, eps);
    offsets_kernel<<<1, 1>>>();
    scatter_kernel<<<16, 256>>>();
    for (int c = 0; c < NCHUNK; c++) {
        gemm1_chunk<<<dim3(16, 8), 256>>>(x, w1, c);
        gemm2_chunk<<<dim3(16, 8), 256>>>(w2, out, c);
    }
    loss_kernel<<<1, 1>>>(out, out_size);
}

// round 15
// speedup vs baseline: 2.8605x; 2.8605x over previous
#include <cuda_runtime.h>
#include <math.h>

#define NTOK 4096
#define DDIM 1024
#define NE 8
#define HDIM 1024
#define SLOTCAP 9216          // 8192 + 8*128 max padding
#define NBLK 148
#define MAXRT 72              // max 128-row tiles: 64 + 8

// ---------------- scratch (device globals; NEVER referenced from host code) ----------------
__device__ int   g_cnt[NE];
__device__ int   g_cnt2[NE];
__device__ int   g_offr[NE];              // 128-aligned slot offsets
__device__ int   g_tile_pfx[NE + 1];      // 128-row-tile prefix
__device__ float g_gates_sum[NE];
__device__ float g_probs_sum[NE];
__device__ float g_zsum;
__device__ int   g_top_i[NTOK * 2];
__device__ float g_top_g[NTOK * 2];
__device__ int   g_tok[SLOTCAP];
__device__ float g_gate[SLOTCAP];
__device__ float g_h[SLOTCAP * HDIM];     // 37.7 MB, device-side use only

// ---------------- zero counters ----------------
__global__ void zero_kernel() {
    int t = threadIdx.x;
    if (t < NE) { g_cnt[t] = 0; g_cnt2[t] = 0; g_gates_sum[t] = 0.f; g_probs_sum[t] = 0.f; }
    if (t == NE) g_zsum = 0.f;
}

// ---------------- persistent zero of out's y region ----------------
__global__ void __launch_bounds__(256) zero_out_kernel(float* __restrict__ out) {
    float4* o4 = (float4*)out;
    const int total = NTOK * DDIM / 4;
    for (int i = blockIdx.x * 256 + threadIdx.x; i < total; i += NBLK * 256)
        o4[i] = make_float4(0.f, 0.f, 0.f, 0.f);
}

// ---------------- gating: logits GEMV + noisy softmax + top2 + loss sums ----------------
__global__ void __launch_bounds__(128) gating_kernel(
        const float* __restrict__ x, const float* __restrict__ wg,
        const float* __restrict__ eps) {
    __shared__ float xs[32][68];
    __shared__ float wgs[16][64];
    __shared__ float sh_logits[32][17];
    __shared__ float sh_probs[NE], sh_gates[NE], sh_z;
    __shared__ int   sh_cnt[NE];

    int tid = threadIdx.x;
    int tq = tid & 31, og = tid >> 5;
    if (tid < NE) { sh_probs[tid] = 0.f; sh_gates[tid] = 0.f; sh_cnt[tid] = 0; }
    if (tid == NE) sh_z = 0.f;

    int tokbase = blockIdx.x * 32;
    float acc0 = 0.f, acc1 = 0.f, acc2 = 0.f, acc3 = 0.f;

    for (int k0 = 0; k0 < DDIM; k0 += 64) {
        __syncthreads();
        #pragma unroll
        for (int idx = tid; idx < 32 * 64; idx += 128) {
            int tk = idx >> 6, kk = idx & 63;
            xs[tk][kk] = x[(size_t)(tokbase + tk) * DDIM + k0 + kk];
        }
        #pragma unroll
        for (int idx = tid; idx < 16 * 64; idx += 128) {
            int o = idx >> 6, kk = idx & 63;
            wgs[o][kk] = wg[(size_t)o * DDIM + k0 + kk];
        }
        __syncthreads();
        #pragma unroll
        for (int kk = 0; kk < 64; kk += 4) {
            float4 xv = *(const float4*)&xs[tq][kk];
            float4 w0 = *(const float4*)&wgs[og * 4 + 0][kk];
            float4 w1v = *(const float4*)&wgs[og * 4 + 1][kk];
            float4 w2v = *(const float4*)&wgs[og * 4 + 2][kk];
            float4 w3 = *(const float4*)&wgs[og * 4 + 3][kk];
            acc0 += xv.x * w0.x + xv.y * w0.y + xv.z * w0.z + xv.w * w0.w;
            acc1 += xv.x * w1v.x + xv.y * w1v.y + xv.z * w1v.z + xv.w * w1v.w;
            acc2 += xv.x * w2v.x + xv.y * w2v.y + xv.z * w2v.z + xv.w * w2v.w;
            acc3 += xv.x * w3.x + xv.y * w3.y + xv.z * w3.z + xv.w * w3.w;
        }
    }
    __syncthreads();
    sh_logits[tq][og * 4 + 0] = acc0;
    sh_logits[tq][og * 4 + 1] = acc1;
    sh_logits[tq][og * 4 + 2] = acc2;
    sh_logits[tq][og * 4 + 3] = acc3;
    __syncthreads();

    if (tid < 32) {
        int n = tokbase + tid;
        auto mk = [&](int e) -> float {
            float clean = sh_logits[tid][e];
            float raw   = sh_logits[tid][e + NE];
            float sp = (raw > 20.f) ? raw : __logf(1.f + __expf(raw));
            return clean + eps[(size_t)n * NE + e] * (sp + 0.01f);
        };
        float l0 = mk(0), l1 = mk(1), l2 = mk(2), l3 = mk(3);
        float l4 = mk(4), l5 = mk(5), l6 = mk(6), l7 = mk(7);

        float mx = fmaxf(fmaxf(fmaxf(l0, l1), fmaxf(l2, l3)),
                         fmaxf(fmaxf(l4, l5), fmaxf(l6, l7)));
        float p0 = __expf(l0 - mx), p1 = __expf(l1 - mx);
        float p2 = __expf(l2 - mx), p3 = __expf(l3 - mx);
        float p4 = __expf(l4 - mx), p5 = __expf(l5 - mx);
        float p6 = __expf(l6 - mx), p7 = __expf(l7 - mx);
        float s = p0 + p1 + p2 + p3 + p4 + p5 + p6 + p7;
        float inv = __fdividef(1.f, s);
        float lse = mx + __logf(s);

        float v0 = -1e30f, v1 = -1e30f;
        int i0 = 0, i1 = 0;
        auto upd = [&](float l, int e) {
            bool gt0 = l > v0;
            bool gt1 = l > v1;
            v1 = gt0 ? v0 : (gt1 ? l : v1);
            i1 = gt0 ? i0 : (gt1 ? e : i1);
            v0 = gt0 ? l : v0;
            i0 = gt0 ? e : i0;
        };
        upd(l0, 0); upd(l1, 1); upd(l2, 2); upd(l3, 3);
        upd(l4, 4); upd(l5, 5); upd(l6, 6); upd(l7, 7);

        float gv0 = __expf(v0 - mx) * inv;
        float gv1 = __expf(v1 - mx) * inv;

        atomicAdd(&sh_probs[0], p0 * inv); atomicAdd(&sh_probs[1], p1 * inv);
        atomicAdd(&sh_probs[2], p2 * inv); atomicAdd(&sh_probs[3], p3 * inv);
        atomicAdd(&sh_probs[4], p4 * inv); atomicAdd(&sh_probs[5], p5 * inv);
        atomicAdd(&sh_probs[6], p6 * inv); atomicAdd(&sh_probs[7], p7 * inv);
        atomicAdd(&sh_z, lse * lse);
        atomicAdd(&sh_gates[i0], gv0);
        atomicAdd(&sh_gates[i1], gv1);
        atomicAdd(&sh_cnt[i0], 1);
        atomicAdd(&sh_cnt[i1], 1);
        g_top_i[2 * n]     = i0;  g_top_g[2 * n]     = gv0;
        g_top_i[2 * n + 1] = i1;  g_top_g[2 * n + 1] = gv1;
    }
    __syncthreads();
    if (tid < NE) {
        atomicAdd(&g_cnt[tid], sh_cnt[tid]);
        atomicAdd(&g_probs_sum[tid], sh_probs[tid]);
        atomicAdd(&g_gates_sum[tid], sh_gates[tid]);
    }
    if (tid == NE) atomicAdd(&g_zsum, sh_z);
}

// ---------------- offsets: 128-aligned prefix + tile prefix ----------------
__global__ void offsets_kernel() {
    int off = 0, tp = 0;
    g_tile_pfx[0] = 0;
    #pragma unroll
    for (int e = 0; e < NE; e++) {
        g_offr[e] = off;
        int rt = (g_cnt[e] + 127) >> 7;
        off += rt << 7;
        tp += rt;
        g_tile_pfx[e + 1] = tp;
    }
}

// ---------------- scatter ----------------
__global__ void __launch_bounds__(256) scatter_kernel() {
    int n = blockIdx.x * 256 + threadIdx.x;
    if (n >= NTOK) return;
    #pragma unroll
    for (int k = 0; k < 2; k++) {
        int e = g_top_i[2 * n + k];
        int pos = atomicAdd(&g_cnt2[e], 1);
        int s = g_offr[e] + pos;
        g_tok[s]  = n;
        g_gate[s] = g_top_g[2 * n + k];
    }
}

// ---------------- tiled fp32 GEMM, 128x128x8, 256 threads, 8x8/thread ----------------
// All g_* referenced from device code only. A source selected inside the kernel:
// GATHER=true : A = x rows gathered via g_tok; C = g_h (relu*gate fused)
// GATHER=false: A = g_h slot rows;            C = atomicAdd into out[tok]
template<bool GATHER>
__global__ void __launch_bounds__(256, 1) gemm_tile(
        const float* __restrict__ Xin, const float* __restrict__ Bbase,
        float* __restrict__ Out) {
    const int rt = blockIdx.y;
    if (rt >= g_tile_pfx[NE]) return;
    int e = 0;
    #pragma unroll
    for (int q = 1; q < NE; q++) if (rt >= g_tile_pfx[q]) e = q;

    const int M = g_cnt[e];
    const int mbase = (rt - g_tile_pfx[e]) << 7;
    const int nbase = blockIdx.x << 7;
    const int offr = g_offr[e];

    const float* Bp = Bbase + (size_t)e * DDIM * HDIM;
    const int* rows = g_tok + offr;

    __shared__ __align__(16) float As[8][128];
    __shared__ __align__(16) float Bs[8][128];

    const int tid = threadIdx.x;
    const int a_row = tid >> 1, a_k = (tid & 1) << 2;
    const int b_k = tid >> 5, b_n = (tid & 31) << 2;
    const int tx = tid & 15, ty = tid >> 4;

    int r_e = min(mbase + a_row, M - 1);
    const float* Arow = GATHER ? (Xin + (size_t)rows[r_e] * 1024 + a_k)
                               : (g_h + (size_t)(offr + r_e) * 1024 + a_k);
    const float* Bptr = Bp + (size_t)b_k * 1024 + nbase + b_n;

    float acc[8][8];
    #pragma unroll
    for (int i = 0; i < 8; i++)
        #pragma unroll
        for (int j = 0; j < 8; j++) acc[i][j] = 0.f;

    for (int k0 = 0; k0 < 1024; k0 += 8) {
        float4 av = *(const float4*)(Arow + k0);
        float4 bv = *(const float4*)(Bptr + (size_t)k0 * 1024);
        __syncthreads();
        As[a_k + 0][a_row] = av.x;
        As[a_k + 1][a_row] = av.y;
        As[a_k + 2][a_row] = av.z;
        As[a_k + 3][a_row] = av.w;
        *(float4*)&Bs[b_k][b_n] = bv;
        __syncthreads();
        #pragma unroll
        for (int k = 0; k < 8; k++) {
            float4 a0 = *(const float4*)&As[k][ty * 8];
            float4 a1 = *(const float4*)&As[k][ty * 8 + 4];
            float4 b0 = *(const float4*)&Bs[k][tx * 8];
            float4 b1 = *(const float4*)&Bs[k][tx * 8 + 4];
            float ar0 = a0.x, ar1 = a0.y, ar2 = a0.z, ar3 = a0.w;
            float ar4 = a1.x, ar5 = a1.y, ar6 = a1.z, ar7 = a1.w;
            float br0 = b0.x, br1 = b0.y, br2 = b0.z, br3 = b0.w;
            float br4 = b1.x, br5 = b1.y, br6 = b1.z, br7 = b1.w;
            acc[0][0] += ar0*br0; acc[0][1] += ar0*br1; acc[0][2] += ar0*br2; acc[0][3] += ar0*br3;
            acc[0][4] += ar0*br4; acc[0][5] += ar0*br5; acc[0][6] += ar0*br6; acc[0][7] += ar0*br7;
            acc[1][0] += ar1*br0; acc[1][1] += ar1*br1; acc[1][2] += ar1*br2; acc[1][3] += ar1*br3;
            acc[1][4] += ar1*br4; acc[1][5] += ar1*br5; acc[1][6] += ar1*br6; acc[1][7] += ar1*br7;
            acc[2][0] += ar2*br0; acc[2][1] += ar2*br1; acc[2][2] += ar2*br2; acc[2][3] += ar2*br3;
            acc[2][4] += ar2*br4; acc[2][5] += ar2*br5; acc[2][6] += ar2*br6; acc[2][7] += ar2*br7;
            acc[3][0] += ar3*br0; acc[3][1] += ar3*br1; acc[3][2] += ar3*br2; acc[3][3] += ar3*br3;
            acc[3][4] += ar3*br4; acc[3][5] += ar3*br5; acc[3][6] += ar3*br6; acc[3][7] += ar3*br7;
            acc[4][0] += ar4*br0; acc[4][1] += ar4*br1; acc[4][2] += ar4*br2; acc[4][3] += ar4*br3;
            acc[4][4] += ar4*br4; acc[4][5] += ar4*br5; acc[4][6] += ar4*br6; acc[4][7] += ar4*br7;
            acc[5][0] += ar5*br0; acc[5][1] += ar5*br1; acc[5][2] += ar5*br2; acc[5][3] += ar5*br3;
            acc[5][4] += ar5*br4; acc[5][5] += ar5*br5; acc[5][6] += ar5*br6; acc[5][7] += ar5*br7;
            acc[6][0] += ar6*br0; acc[6][1] += ar6*br1; acc[6][2] += ar6*br2; acc[6][3] += ar6*br3;
            acc[6][4] += ar6*br4; acc[6][5] += ar6*br5; acc[6][6] += ar6*br6; acc[6][7] += ar6*br7;
            acc[7][0] += ar7*br0; acc[7][1] += ar7*br1; acc[7][2] += ar7*br2; acc[7][3] += ar7*br3;
            acc[7][4] += ar7*br4; acc[7][5] += ar7*br5; acc[7][6] += ar7*br6; acc[7][7] += ar7*br7;
        }
    }

    #pragma unroll
    for (int i = 0; i < 8; i++) {
        int gm = mbase + ty * 8 + i;
        if (gm < M) {
            if (GATHER) {
                float g = g_gate[offr + gm];
                float* Crow = g_h + (size_t)(offr + gm) * 1024 + nbase + tx * 8;
                float4 v0, v1;
                v0.x = fmaxf(acc[i][0], 0.f) * g; v0.y = fmaxf(acc[i][1], 0.f) * g;
                v0.z = fmaxf(acc[i][2], 0.f) * g; v0.w = fmaxf(acc[i][3], 0.f) * g;
                v1.x = fmaxf(acc[i][4], 0.f) * g; v1.y = fmaxf(acc[i][5], 0.f) * g;
                v1.z = fmaxf(acc[i][6], 0.f) * g; v1.w = fmaxf(acc[i][7], 0.f) * g;
                *(float4*)Crow       = v0;
                *(float4*)(Crow + 4) = v1;
            } else {
                float* d = Out + (size_t)rows[gm] * 1024 + nbase + tx * 8;
                atomicAdd(d + 0, acc[i][0]); atomicAdd(d + 1, acc[i][1]);
                atomicAdd(d + 2, acc[i][2]); atomicAdd(d + 3, acc[i][3]);
                atomicAdd(d + 4, acc[i][4]); atomicAdd(d + 5, acc[i][5]);
                atomicAdd(d + 6, acc[i][6]); atomicAdd(d + 7, acc[i][7]);
            }
        }
    }
}

// ---------------- loss finalize ----------------
__global__ void loss_kernel(float* __restrict__ out, int out_size) {
    if (out_size <= NTOK * DDIM) return;
    float T = 0.f, P = 0.f, C = 0.f;
    #pragma unroll
    for (int e = 0; e < NE; e++) {
        T += fabsf(g_gates_sum[e]);
        P += fabsf(g_probs_sum[e]);
        C += fabsf((float)g_cnt[e]);
    }
    T = fmaxf(T, 1e-12f); P = fmaxf(P, 1e-12f); C = fmaxf(C, 1e-12f);
    float rT = __fdividef(1.f, T);
    float rP = __fdividef(1.f, P);
    float rC = __fdividef(1.f, C);
    float mean = 0.f;
    #pragma unroll
    for (int e = 0; e < NE; e++) mean += g_gates_sum[e] * rT;
    mean *= 0.125f;
    float var = 0.f;
    #pragma unroll
    for (int e = 0; e < NE; e++) {
        float d = g_gates_sum[e] * rT - mean;
        var += d * d;
    }
    var *= (1.f / (float)(NE - 1));
    float cv = __fdividef(var, mean * mean + 1e-10f);
    float sw = 0.f;
    #pragma unroll
    for (int e = 0; e < NE; e++)
        sw += (g_probs_sum[e] * rP) * ((float)g_cnt[e] * rC);
    sw = (1.f - sw) * (float)NE;
    float z = g_zsum * (1.f / (float)NTOK);
    out[NTOK * DDIM] = 0.01f * cv + 0.1f * sw + 0.0001f * z;
}

// ---------------- launch (NO __device__ symbols referenced here) ----------------
extern "C" void kernel_launch(void* const* d_in, const int* in_sizes, int n_in,
                              void* d_out, int out_size) {
    const float* x   = (const float*)d_in[0];
    const float* wg  = (const float*)d_in[1];
    const float* w1  = (const float*)d_in[2];
    const float* w2  = (const float*)d_in[3];
    const float* eps = (const float*)d_in[4];
    float* out = (float*)d_out;

    zero_kernel<<<1, 32>>>();
    zero_out_kernel<<<NBLK, 256>>>(out);
    gating_kernel<<<128, 128>>>(x, wg, eps);
    offsets_kernel<<<1, 1>>>();
    scatter_kernel<<<16, 256>>>();
    gemm_tile<true ><<<dim3(8, MAXRT), 256>>>(x, w1, nullptr);
    gemm_tile<false><<<dim3(8, MAXRT), 256>>>(x, w2, out);
    loss_kernel<<<1, 1>>>(out, out_size);
}

// round 17
// speedup vs baseline: 2.9242x; 1.0223x over previous
#include <cuda_runtime.h>
#include <math.h>

#define NTOK 4096
#define DDIM 1024
#define NE 8
#define HDIM 1024
#define SLOTCAP 9216          // 8192 + 8*128 max padding
#define NBLK 148
#define MAXRT 72              // max 128-row tiles: 64 + 8

// packed fp32x2 helpers (Blackwell f32x2 pipe; ptxas never auto-fuses these)
#define PACKDUP(dst, s) asm("mov.b64 %0, {%1, %1};" : "=l"(dst) : "f"(s))
#define FMA2(c, a, b)   asm("fma.rn.f32x2 %0, %1, %2, %0;" : "+l"(c) : "l"(a), "l"(b))
#define UNPACK2(lo, hi, v) asm("mov.b64 {%0, %1}, %2;" : "=f"(lo), "=f"(hi) : "l"(v))

// ---------------- scratch (device globals; NEVER referenced from host code) ----------------
__device__ int   g_cnt[NE];
__device__ int   g_cnt2[NE];
__device__ int   g_offr[NE];              // 128-aligned slot offsets
__device__ int   g_tile_pfx[NE + 1];      // 128-row-tile prefix
__device__ float g_gates_sum[NE];
__device__ float g_probs_sum[NE];
__device__ float g_zsum;
__device__ int   g_top_i[NTOK * 2];
__device__ float g_top_g[NTOK * 2];
__device__ int   g_tok[SLOTCAP];
__device__ float g_gate[SLOTCAP];
__device__ float g_h[SLOTCAP * HDIM];     // 37.7 MB, device-side use only

// ---------------- zero counters ----------------
__global__ void zero_kernel() {
    int t = threadIdx.x;
    if (t < NE) { g_cnt[t] = 0; g_cnt2[t] = 0; g_gates_sum[t] = 0.f; g_probs_sum[t] = 0.f; }
    if (t == NE) g_zsum = 0.f;
}

// ---------------- persistent zero of out's y region ----------------
__global__ void __launch_bounds__(256) zero_out_kernel(float* __restrict__ out) {
    float4* o4 = (float4*)out;
    const int total = NTOK * DDIM / 4;
    for (int i = blockIdx.x * 256 + threadIdx.x; i < total; i += NBLK * 256)
        o4[i] = make_float4(0.f, 0.f, 0.f, 0.f);
}

// ---------------- gating: logits GEMV + noisy softmax + top2 + loss sums ----------------
__global__ void __launch_bounds__(128) gating_kernel(
        const float* __restrict__ x, const float* __restrict__ wg,
        const float* __restrict__ eps) {
    __shared__ float xs[32][68];
    __shared__ float wgs[16][64];
    __shared__ float sh_logits[32][17];
    __shared__ float sh_probs[NE], sh_gates[NE], sh_z;
    __shared__ int   sh_cnt[NE];

    int tid = threadIdx.x;
    int tq = tid & 31, og = tid >> 5;
    if (tid < NE) { sh_probs[tid] = 0.f; sh_gates[tid] = 0.f; sh_cnt[tid] = 0; }
    if (tid == NE) sh_z = 0.f;

    int tokbase = blockIdx.x * 32;
    float acc0 = 0.f, acc1 = 0.f, acc2 = 0.f, acc3 = 0.f;

    for (int k0 = 0; k0 < DDIM; k0 += 64) {
        __syncthreads();
        #pragma unroll
        for (int idx = tid; idx < 32 * 64; idx += 128) {
            int tk = idx >> 6, kk = idx & 63;
            xs[tk][kk] = x[(size_t)(tokbase + tk) * DDIM + k0 + kk];
        }
        #pragma unroll
        for (int idx = tid; idx < 16 * 64; idx += 128) {
            int o = idx >> 6, kk = idx & 63;
            wgs[o][kk] = wg[(size_t)o * DDIM + k0 + kk];
        }
        __syncthreads();
        #pragma unroll
        for (int kk = 0; kk < 64; kk += 4) {
            float4 xv = *(const float4*)&xs[tq][kk];
            float4 w0 = *(const float4*)&wgs[og * 4 + 0][kk];
            float4 w1v = *(const float4*)&wgs[og * 4 + 1][kk];
            float4 w2v = *(const float4*)&wgs[og * 4 + 2][kk];
            float4 w3 = *(const float4*)&wgs[og * 4 + 3][kk];
            acc0 += xv.x * w0.x + xv.y * w0.y + xv.z * w0.z + xv.w * w0.w;
            acc1 += xv.x * w1v.x + xv.y * w1v.y + xv.z * w1v.z + xv.w * w1v.w;
            acc2 += xv.x * w2v.x + xv.y * w2v.y + xv.z * w2v.z + xv.w * w2v.w;
            acc3 += xv.x * w3.x + xv.y * w3.y + xv.z * w3.z + xv.w * w3.w;
        }
    }
    __syncthreads();
    sh_logits[tq][og * 4 + 0] = acc0;
    sh_logits[tq][og * 4 + 1] = acc1;
    sh_logits[tq][og * 4 + 2] = acc2;
    sh_logits[tq][og * 4 + 3] = acc3;
    __syncthreads();

    if (tid < 32) {
        int n = tokbase + tid;
        auto mk = [&](int e) -> float {
            float clean = sh_logits[tid][e];
            float raw   = sh_logits[tid][e + NE];
            float sp = (raw > 20.f) ? raw : __logf(1.f + __expf(raw));
            return clean + eps[(size_t)n * NE + e] * (sp + 0.01f);
        };
        float l0 = mk(0), l1 = mk(1), l2 = mk(2), l3 = mk(3);
        float l4 = mk(4), l5 = mk(5), l6 = mk(6), l7 = mk(7);

        float mx = fmaxf(fmaxf(fmaxf(l0, l1), fmaxf(l2, l3)),
                         fmaxf(fmaxf(l4, l5), fmaxf(l6, l7)));
        float p0 = __expf(l0 - mx), p1 = __expf(l1 - mx);
        float p2 = __expf(l2 - mx), p3 = __expf(l3 - mx);
        float p4 = __expf(l4 - mx), p5 = __expf(l5 - mx);
        float p6 = __expf(l6 - mx), p7 = __expf(l7 - mx);
        float s = p0 + p1 + p2 + p3 + p4 + p5 + p6 + p7;
        float inv = __fdividef(1.f, s);
        float lse = mx + __logf(s);

        float v0 = -1e30f, v1 = -1e30f;
        int i0 = 0, i1 = 0;
        auto upd = [&](float l, int e) {
            bool gt0 = l > v0;
            bool gt1 = l > v1;
            v1 = gt0 ? v0 : (gt1 ? l : v1);
            i1 = gt0 ? i0 : (gt1 ? e : i1);
            v0 = gt0 ? l : v0;
            i0 = gt0 ? e : i0;
        };
        upd(l0, 0); upd(l1, 1); upd(l2, 2); upd(l3, 3);
        upd(l4, 4); upd(l5, 5); upd(l6, 6); upd(l7, 7);

        float gv0 = __expf(v0 - mx) * inv;
        float gv1 = __expf(v1 - mx) * inv;

        atomicAdd(&sh_probs[0], p0 * inv); atomicAdd(&sh_probs[1], p1 * inv);
        atomicAdd(&sh_probs[2], p2 * inv); atomicAdd(&sh_probs[3], p3 * inv);
        atomicAdd(&sh_probs[4], p4 * inv); atomicAdd(&sh_probs[5], p5 * inv);
        atomicAdd(&sh_probs[6], p6 * inv); atomicAdd(&sh_probs[7], p7 * inv);
        atomicAdd(&sh_z, lse * lse);
        atomicAdd(&sh_gates[i0], gv0);
        atomicAdd(&sh_gates[i1], gv1);
        atomicAdd(&sh_cnt[i0], 1);
        atomicAdd(&sh_cnt[i1], 1);
        g_top_i[2 * n]     = i0;  g_top_g[2 * n]     = gv0;
        g_top_i[2 * n + 1] = i1;  g_top_g[2 * n + 1] = gv1;
    }
    __syncthreads();
    if (tid < NE) {
        atomicAdd(&g_cnt[tid], sh_cnt[tid]);
        atomicAdd(&g_probs_sum[tid], sh_probs[tid]);
        atomicAdd(&g_gates_sum[tid], sh_gates[tid]);
    }
    if (tid == NE) atomicAdd(&g_zsum, sh_z);
}

// ---------------- offsets: 128-aligned prefix + tile prefix ----------------
__global__ void offsets_kernel() {
    int off = 0, tp = 0;
    g_tile_pfx[0] = 0;
    #pragma unroll
    for (int e = 0; e < NE; e++) {
        g_offr[e] = off;
        int rt = (g_cnt[e] + 127) >> 7;
        off += rt << 7;
        tp += rt;
        g_tile_pfx[e + 1] = tp;
    }
}

// ---------------- scatter ----------------
__global__ void __launch_bounds__(256) scatter_kernel() {
    int n = blockIdx.x * 256 + threadIdx.x;
    if (n >= NTOK) return;
    #pragma unroll
    for (int k = 0; k < 2; k++) {
        int e = g_top_i[2 * n + k];
        int pos = atomicAdd(&g_cnt2[e], 1);
        int s = g_offr[e] + pos;
        g_tok[s]  = n;
        g_gate[s] = g_top_g[2 * n + k];
    }
}

// ---------------- tiled GEMM, 128x128x8, 256 threads, 8x8/thread via fma.rn.f32x2 ----------------
// GATHER=true : A = x rows gathered via g_tok; C = g_h (relu*gate fused)
// GATHER=false: A = g_h slot rows;            C = atomicAdd into out[tok]
template<bool GATHER>
__global__ void __launch_bounds__(256, 1) gemm_tile(
        const float* __restrict__ Xin, const float* __restrict__ Bbase,
        float* __restrict__ Out) {
    const int rt = blockIdx.y;
    if (rt >= g_tile_pfx[NE]) return;
    int e = 0;
    #pragma unroll
    for (int q = 1; q < NE; q++) if (rt >= g_tile_pfx[q]) e = q;

    const int M = g_cnt[e];
    const int mbase = (rt - g_tile_pfx[e]) << 7;
    const int nbase = blockIdx.x << 7;
    const int offr = g_offr[e];

    const float* Bp = Bbase + (size_t)e * DDIM * HDIM;
    const int* rows = g_tok + offr;

    __shared__ __align__(16) float As[8][128];
    __shared__ __align__(16) float Bs[8][128];

    const int tid = threadIdx.x;
    const int a_row = tid >> 1, a_k = (tid & 1) << 2;
    const int b_k = tid >> 5, b_n = (tid & 31) << 2;
    const int tx = tid & 15, ty = tid >> 4;

    int r_e = min(mbase + a_row, M - 1);
    const float* Arow = GATHER ? (Xin + (size_t)rows[r_e] * 1024 + a_k)
                               : (g_h + (size_t)(offr + r_e) * 1024 + a_k);
    const float* Bptr = Bp + (size_t)b_k * 1024 + nbase + b_n;

    // 8 rows x 4 column-pairs of packed f32x2 accumulators
    unsigned long long acc2[8][4];
    #pragma unroll
    for (int i = 0; i < 8; i++)
        #pragma unroll
        for (int j = 0; j < 4; j++) acc2[i][j] = 0ULL;

    for (int k0 = 0; k0 < 1024; k0 += 8) {
        float4 av = *(const float4*)(Arow + k0);
        float4 bv = *(const float4*)(Bptr + (size_t)k0 * 1024);
        __syncthreads();
        As[a_k + 0][a_row] = av.x;
        As[a_k + 1][a_row] = av.y;
        As[a_k + 2][a_row] = av.z;
        As[a_k + 3][a_row] = av.w;
        *(float4*)&Bs[b_k][b_n] = bv;
        __syncthreads();
        #pragma unroll
        for (int k = 0; k < 8; k++) {
            float4 a0 = *(const float4*)&As[k][ty * 8];
            float4 a1 = *(const float4*)&As[k][ty * 8 + 4];
            const unsigned long long* bp = (const unsigned long long*)&Bs[k][tx * 8];
            unsigned long long b0 = bp[0], b1 = bp[1], b2 = bp[2], b3 = bp[3];
            unsigned long long ap;
            PACKDUP(ap, a0.x);
            FMA2(acc2[0][0], ap, b0); FMA2(acc2[0][1], ap, b1); FMA2(acc2[0][2], ap, b2); FMA2(acc2[0][3], ap, b3);
            PACKDUP(ap, a0.y);
            FMA2(acc2[1][0], ap, b0); FMA2(acc2[1][1], ap, b1); FMA2(acc2[1][2], ap, b2); FMA2(acc2[1][3], ap, b3);
            PACKDUP(ap, a0.z);
            FMA2(acc2[2][0], ap, b0); FMA2(acc2[2][1], ap, b1); FMA2(acc2[2][2], ap, b2); FMA2(acc2[2][3], ap, b3);
            PACKDUP(ap, a0.w);
            FMA2(acc2[3][0], ap, b0); FMA2(acc2[3][1], ap, b1); FMA2(acc2[3][2], ap, b2); FMA2(acc2[3][3], ap, b3);
            PACKDUP(ap, a1.x);
            FMA2(acc2[4][0], ap, b0); FMA2(acc2[4][1], ap, b1); FMA2(acc2[4][2], ap, b2); FMA2(acc2[4][3], ap, b3);
            PACKDUP(ap, a1.y);
            FMA2(acc2[5][0], ap, b0); FMA2(acc2[5][1], ap, b1); FMA2(acc2[5][2], ap, b2); FMA2(acc2[5][3], ap, b3);
            PACKDUP(ap, a1.z);
            FMA2(acc2[6][0], ap, b0); FMA2(acc2[6][1], ap, b1); FMA2(acc2[6][2], ap, b2); FMA2(acc2[6][3], ap, b3);
            PACKDUP(ap, a1.w);
            FMA2(acc2[7][0], ap, b0); FMA2(acc2[7][1], ap, b1); FMA2(acc2[7][2], ap, b2); FMA2(acc2[7][3], ap, b3);
        }
    }

    #pragma unroll
    for (int i = 0; i < 8; i++) {
        int gm = mbase + ty * 8 + i;
        if (gm < M) {
            float c0, c1, c2, c3, c4, c5, c6, c7;
            UNPACK2(c0, c1, acc2[i][0]);
            UNPACK2(c2, c3, acc2[i][1]);
            UNPACK2(c4, c5, acc2[i][2]);
            UNPACK2(c6, c7, acc2[i][3]);
            if (GATHER) {
                float g = g_gate[offr + gm];
                float* Crow = g_h + (size_t)(offr + gm) * 1024 + nbase + tx * 8;
                float4 v0, v1;
                v0.x = fmaxf(c0, 0.f) * g; v0.y = fmaxf(c1, 0.f) * g;
                v0.z = fmaxf(c2, 0.f) * g; v0.w = fmaxf(c3, 0.f) * g;
                v1.x = fmaxf(c4, 0.f) * g; v1.y = fmaxf(c5, 0.f) * g;
                v1.z = fmaxf(c6, 0.f) * g; v1.w = fmaxf(c7, 0.f) * g;
                *(float4*)Crow       = v0;
                *(float4*)(Crow + 4) = v1;
            } else {
                float* d = Out + (size_t)rows[gm] * 1024 + nbase + tx * 8;
                atomicAdd(d + 0, c0); atomicAdd(d + 1, c1);
                atomicAdd(d + 2, c2); atomicAdd(d + 3, c3);
                atomicAdd(d + 4, c4); atomicAdd(d + 5, c5);
                atomicAdd(d + 6, c6); atomicAdd(d + 7, c7);
            }
        }
    }
}

// ---------------- loss finalize ----------------
__global__ void loss_kernel(float* __restrict__ out, int out_size) {
    if (out_size <= NTOK * DDIM) return;
    float T = 0.f, P = 0.f, C = 0.f;
    #pragma unroll
    for (int e = 0; e < NE; e++) {
        T += fabsf(g_gates_sum[e]);
        P += fabsf(g_probs_sum[e]);
        C += fabsf((float)g_cnt[e]);
    }
    T = fmaxf(T, 1e-12f); P = fmaxf(P, 1e-12f); C = fmaxf(C, 1e-12f);
    float rT = __fdividef(1.f, T);
    float rP = __fdividef(1.f, P);
    float rC = __fdividef(1.f, C);
    float mean = 0.f;
    #pragma unroll
    for (int e = 0; e < NE; e++) mean += g_gates_sum[e] * rT;
    mean *= 0.125f;
    float var = 0.f;
    #pragma unroll
    for (int e = 0; e < NE; e++) {
        float d = g_gates_sum[e] * rT - mean;
        var += d * d;
    }
    var *= (1.f / (float)(NE - 1));
    float cv = __fdividef(var, mean * mean + 1e-10f);
    float sw = 0.f;
    #pragma unroll
    for (int e = 0; e < NE; e++)
        sw += (g_probs_sum[e] * rP) * ((float)g_cnt[e] * rC);
    sw = (1.f - sw) * (float)NE;
    float z = g_zsum * (1.f / (float)NTOK);
    out[NTOK * DDIM] = 0.01f * cv + 0.1f * sw + 0.0001f * z;
}

// ---------------- launch (NO __device__ symbols referenced here) ----------------
extern "C" void kernel_launch(void* const* d_in, const int* in_sizes, int n_in,
                              void* d_out, int out_size) {
    const float* x   = (const float*)d_in[0];
    const float* wg  = (const float*)d_in[1];
    const float* w1  = (const float*)d_in[2];
    const float* w2  = (const float*)d_in[3];
    const float* eps = (const float*)d_in[4];
    float* out = (float*)d_out;

    zero_kernel<<<1, 32>>>();
    zero_out_kernel<<<NBLK, 256>>>(out);
    gating_kernel<<<128, 128>>>(x, wg, eps);
    offsets_kernel<<<1, 1>>>();
    scatter_kernel<<<16, 256>>>();
    gemm_tile<true ><<<dim3(8, MAXRT), 256>>>(x, w1, nullptr);
    gemm_tile<false><<<dim3(8, MAXRT), 256>>>(x, w2, out);
    loss_kernel<<<1, 1>>>(out, out_size);
}